// round 12
// baseline (speedup 1.0000x reference)
#include <cuda_runtime.h>
#include <cuda_fp16.h>
#include <math.h>
#include <stdint.h>

#define BATCH 4
#define SEQ   2048
#define CH    1024
#define NHEAD 16
#define DK    64
#define C3    3072
#define ROWS  (BATCH*SEQ)   // 8192

// ---------------- scratch ----------------
__device__ __align__(16) __half g_qkvh[(size_t)ROWS * C3];
__device__ __align__(16) __half g_attnh[(size_t)ROWS * CH];
__device__ __align__(16) __half g_xh[(size_t)ROWS * CH];
__device__ __align__(16) __half g_wqkvh[(size_t)CH * C3];   // [K,N] natural layout
__device__ __align__(16) __half g_wouth[(size_t)CH * CH];   // [K,N] natural layout

// ---------------- helpers ----------------
__device__ __forceinline__ void cp_async16(void* smem_dst, const void* gmem_src) {
    unsigned s = (unsigned)__cvta_generic_to_shared(smem_dst);
    asm volatile("cp.async.cg.shared.global [%0], [%1], 16;\n" :: "r"(s), "l"(gmem_src));
}
__device__ __forceinline__ void cp_commit() {
    asm volatile("cp.async.commit_group;\n" ::);
}
template<int N>
__device__ __forceinline__ void cp_wait() {
    asm volatile("cp.async.wait_group %0;\n" :: "n"(N));
}
__device__ __forceinline__ void mma_f16(float c[4], const uint32_t a[4], uint32_t b0, uint32_t b1) {
    asm volatile(
        "mma.sync.aligned.m16n8k16.row.col.f32.f16.f16.f32 "
        "{%0,%1,%2,%3}, {%4,%5,%6,%7}, {%8,%9}, {%0,%1,%2,%3};"
        : "+f"(c[0]), "+f"(c[1]), "+f"(c[2]), "+f"(c[3])
        : "r"(a[0]), "r"(a[1]), "r"(a[2]), "r"(a[3]), "r"(b0), "r"(b1));
}
__device__ __forceinline__ uint32_t pack_h2(float x, float y) {
    __half2 h = __floats2half2_rn(x, y);
    return *reinterpret_cast<uint32_t*>(&h);
}
__device__ __forceinline__ uint32_t h2exp2_u(uint32_t d2) {
    uint32_t r;
    asm("ex2.approx.f16x2 %0, %1;" : "=r"(r) : "r"(d2));
    return r;
}
__device__ __forceinline__ float ex2f_(float x) {
    float r;
    asm("ex2.approx.f32 %0, %1;" : "=f"(r) : "f"(x));
    return r;
}
__device__ __forceinline__ void ldm_x4(uint32_t& r0, uint32_t& r1, uint32_t& r2, uint32_t& r3,
                                       const __half* p) {
    uint32_t addr = (uint32_t)__cvta_generic_to_shared(p);
    asm volatile("ldmatrix.sync.aligned.m8n8.x4.shared.b16 {%0,%1,%2,%3}, [%4];"
        : "=r"(r0), "=r"(r1), "=r"(r2), "=r"(r3) : "r"(addr));
}
__device__ __forceinline__ void ldm_x4_t(uint32_t& r0, uint32_t& r1, uint32_t& r2, uint32_t& r3,
                                         const __half* p) {
    uint32_t addr = (uint32_t)__cvta_generic_to_shared(p);
    asm volatile("ldmatrix.sync.aligned.m8n8.x4.trans.shared.b16 {%0,%1,%2,%3}, [%4];"
        : "=r"(r0), "=r"(r1), "=r"(r2), "=r"(r3) : "r"(addr));
}

// ---------------- fused pre-pass: fp32 -> fp16 for x, w_qkv, w_out ----------------
__global__ void f2h3_kernel(const float4* __restrict__ a, __half2* __restrict__ ah, int na,
                            const float4* __restrict__ b, __half2* __restrict__ bh, int nb,
                            const float4* __restrict__ c, __half2* __restrict__ ch, int nc)
{
    int i = blockIdx.x * blockDim.x + threadIdx.x;
    const int stride = gridDim.x * blockDim.x;
    const int tot = na + nb + nc;
    for (; i < tot; i += stride) {
        const float4* src;
        __half2* dst;
        int k;
        if (i < na)            { src = a; dst = ah; k = i; }
        else if (i < na + nb)  { src = b; dst = bh; k = i - na; }
        else                   { src = c; dst = ch; k = i - na - nb; }
        float4 v = src[k];
        dst[2 * k]     = __floats2half2_rn(v.x, v.y);
        dst[2 * k + 1] = __floats2half2_rn(v.z, v.w);
    }
}

// ---------------- fp16 GEMM: C[M,N] = A[M,K] @ B[K,N] ----------------
// CTA 128xTN, 4 warps of 64x(TN/2), TK=32, 4-stage cp.async, one barrier/stage.
// Per-CTA K-loop phase rotation (parity of bx^by starts at K/2) to desync the
// two resident CTAs' barrier/fill walls.
#define GTK 32
#define GALD 40
#define G_ASTG (128 * GALD)           // 5120 halves

template<bool HALF_OUT, int TN>
__global__ void __launch_bounds__(128, 2) gemm_f16_kernel(
    const __half* __restrict__ A, const __half* __restrict__ B,
    void* __restrict__ Cout, int Ntot, int K)
{
    constexpr int WN   = TN / 2;
    constexpr int NT   = WN / 8;
    constexpr int NG   = WN / 16;
    constexpr int BLD  = TN + 8;
    constexpr int BSTG = GTK * BLD;
    constexpr int STG  = G_ASTG + BSTG;

    extern __shared__ __half sh[];
    const int tid = threadIdx.x;
    const int lane = tid & 31;
    const int wid = tid >> 5;
    const int wm = wid & 1;
    const int wn = wid >> 1;
    const int m0 = blockIdx.y * 128;
    const int n0 = blockIdx.x * TN;
    const int KT = K / GTK;
    const int g = lane >> 2;
    const int c2 = 2 * (lane & 3);

    const int a_row = lane & 15;
    const int a_ko  = (lane >> 4) * 8;
    const int vt_row = ((lane >> 3) & 1) * 8 + (lane & 7);
    const int vt_co  = (lane >> 4) * 8;

    // phase offset: odd-parity CTAs start halfway through K and wrap
    const int kph = ((blockIdx.x ^ blockIdx.y) & 1) * (KT / 2);

    auto fill = [&](int buf, int s) {
        __half* As = sh + buf * STG;
        __half* Bs = As + G_ASTG;
        int sk = s + kph;
        if (sk >= KT) sk -= KT;
        const int k0 = sk * GTK;
        #pragma unroll
        for (int j = 0; j < 4; j++) {
            int c = tid + j * 128;
            int row = c >> 2, chh = (c & 3) << 3;
            cp_async16(As + row * GALD + chh, A + (size_t)(m0 + row) * K + k0 + chh);
        }
        #pragma unroll
        for (int j = 0; j < TN / 32; j++) {
            int c = tid + j * 128;
            int row = c / (TN / 8);
            int chh = (c % (TN / 8)) * 8;
            cp_async16(Bs + row * BLD + chh, B + (size_t)(k0 + row) * Ntot + n0 + chh);
        }
    };

    float acc[4][NT][4];
    #pragma unroll
    for (int i = 0; i < 4; i++)
        #pragma unroll
        for (int j = 0; j < NT; j++)
            #pragma unroll
            for (int e = 0; e < 4; e++) acc[i][j][e] = 0.0f;

    fill(0, 0); cp_commit();
    fill(1, 1); cp_commit();
    fill(2, 2); cp_commit();

    for (int s = 0; s < KT; s++) {
        cp_wait<2>();
        __syncthreads();
        if (s + 3 < KT) fill((s + 3) & 3, s + 3);
        cp_commit();

        const __half* As = sh + (s & 3) * STG;
        const __half* Bs = As + G_ASTG;

        #pragma unroll
        for (int kk = 0; kk < 2; kk++) {
            uint32_t a[4][4];
            #pragma unroll
            for (int mt = 0; mt < 4; mt++)
                ldm_x4(a[mt][0], a[mt][1], a[mt][2], a[mt][3],
                       As + (wm * 64 + mt * 16 + a_row) * GALD + kk * 16 + a_ko);

            uint32_t bf[NT][2];
            #pragma unroll
            for (int ng = 0; ng < NG; ng++)
                ldm_x4_t(bf[2 * ng][0], bf[2 * ng][1], bf[2 * ng + 1][0], bf[2 * ng + 1][1],
                         Bs + (kk * 16 + vt_row) * BLD + wn * WN + ng * 16 + vt_co);

            #pragma unroll
            for (int mt = 0; mt < 4; mt++)
                #pragma unroll
                for (int nt = 0; nt < NT; nt++)
                    mma_f16(acc[mt][nt], a[mt], bf[nt][0], bf[nt][1]);
        }
    }

    #pragma unroll
    for (int mt = 0; mt < 4; mt++) {
        #pragma unroll
        for (int nt = 0; nt < NT; nt++) {
            const int row = m0 + wm * 64 + mt * 16 + g;
            const int col = n0 + wn * WN + nt * 8 + c2;
            if (HALF_OUT) {
                __half* Ch = (__half*)Cout;
                *reinterpret_cast<__half2*>(Ch + (size_t)row * Ntot + col) =
                    __floats2half2_rn(acc[mt][nt][0], acc[mt][nt][1]);
                *reinterpret_cast<__half2*>(Ch + (size_t)(row + 8) * Ntot + col) =
                    __floats2half2_rn(acc[mt][nt][2], acc[mt][nt][3]);
            } else {
                float* Cf = (float*)Cout;
                *reinterpret_cast<float2*>(Cf + (size_t)row * Ntot + col) =
                    make_float2(acc[mt][nt][0], acc[mt][nt][1]);
                *reinterpret_cast<float2*>(Cf + (size_t)(row + 8) * Ntot + col) =
                    make_float2(acc[mt][nt][2], acc[mt][nt][3]);
            }
        }
    }
}

#define GEMM_SMEM_128 ((G_ASTG + GTK * 136) * 2 * 4)   // 75776 bytes

// ---------------- Flash attention: 128 q-rows, 4 warps x 32 rows ----------------
// h2exp softmax (log2 domain), row sums via ones-column in V, warp-vote rescale skip.
#define BQ 128
#define AT_LD 88
#define KV_TILE (64 * AT_LD)                        // 5632 halves
#define AT_BUF (2 * KV_TILE)                        // 11264 halves per stage
#define AT_SMEM_HALVES (3 * AT_BUF + BQ * AT_LD)    // 45056
#define AT_SMEM_BYTES (AT_SMEM_HALVES * 2)          // 90112
#define L2E 1.4426950408889634f

__global__ void __launch_bounds__(128, 2) attn_kernel(
    const __half* __restrict__ qkvh, __half* __restrict__ out)
{
    extern __shared__ __half smh[];
    const int tid = threadIdx.x;
    const int lane = tid & 31;
    const int w = tid >> 5;
    const int g = lane >> 2;
    const int c2 = 2 * (lane & 3);
    const int qt = gridDim.x - 1 - blockIdx.x;
    const int bh = blockIdx.y;
    const int b = bh >> 4;
    const int h = bh & 15;

    const int a_row = lane & 15;
    const int a_ko  = (lane >> 4) * 8;
    const int b_row = ((lane >> 4) * 8) + (lane & 7);
    const int b_ko  = ((lane >> 3) & 1) * 8;
    const int vt_row = ((lane >> 3) & 1) * 8 + (lane & 7);
    const int vt_co  = (lane >> 4) * 8;

    __half* Qs = smh + 3 * AT_BUF;
    const int NJ = 2 * qt + 2;

    auto fill = [&](int buf, int j) {
        __half* K = smh + buf * AT_BUF;
        __half* V = K + KV_TILE;
        const __half* kg = qkvh + (size_t)(b * SEQ + j * 64) * C3 + CH + h * 64;
        #pragma unroll
        for (int i = 0; i < 4; i++) {
            int f = tid + i * 128;
            int r = f >> 3, ch = (f & 7) << 3;
            const __half* src = kg + (size_t)r * C3 + ch;
            cp_async16(K + r * AT_LD + ch, src);
            cp_async16(V + r * AT_LD + ch, src + CH);
        }
    };

    fill(0, 0); cp_commit();
    if (NJ > 1) fill(1, 1);
    cp_commit();

    // Init V pad columns (64..87) of all 3 buffers: col 64 = 1 (l-column), rest 0.
    for (int idx = tid; idx < 3 * 64 * 24; idx += 128) {
        int bufi = idx / (64 * 24);
        int rr = (idx % (64 * 24)) / 24;
        int cc = idx % 24;
        smh[bufi * AT_BUF + KV_TILE + rr * AT_LD + 64 + cc] =
            (cc == 0) ? __float2half(1.0f) : __float2half(0.0f);
    }

    // Q tile
    {
        const __half* gq = qkvh + (size_t)(b * SEQ + qt * BQ) * C3 + h * 64;
        #pragma unroll
        for (int f = tid; f < 1024; f += 128) {
            int r = f >> 3, ch = (f & 7) << 3;
            *reinterpret_cast<uint4*>(Qs + r * AT_LD + ch) =
                *reinterpret_cast<const uint4*>(gq + (size_t)r * C3 + ch);
        }
    }
    __syncthreads();

    // Q a-fragments, scaled by 1/8 (exact in fp16)
    uint32_t aq[2][4][4];
    {
        const __half2 sc8 = __float2half2_rn(0.125f);
        #pragma unroll
        for (int mt = 0; mt < 2; mt++)
            #pragma unroll
            for (int kk = 0; kk < 4; kk++) {
                ldm_x4(aq[mt][kk][0], aq[mt][kk][1], aq[mt][kk][2], aq[mt][kk][3],
                       Qs + (w * 32 + mt * 16 + a_row) * AT_LD + kk * 16 + a_ko);
                #pragma unroll
                for (int e = 0; e < 4; e++) {
                    __half2 v = *reinterpret_cast<__half2*>(&aq[mt][kk][e]);
                    v = __hmul2(v, sc8);
                    aq[mt][kk][e] = *reinterpret_cast<uint32_t*>(&v);
                }
            }
    }

    // oc[mt][0..7] = O accumulators; oc[mt][8] = l column
    float oc[2][9][4];
    #pragma unroll
    for (int mt = 0; mt < 2; mt++)
        #pragma unroll
        for (int t = 0; t < 9; t++)
            #pragma unroll
            for (int e = 0; e < 4; e++) oc[mt][t][e] = 0.0f;
    float mA[2] = {-INFINITY, -INFINITY}, mB[2] = {-INFINITY, -INFINITY};

    const int qrow0 = qt * BQ + w * 32;

    int buf = 0;
    for (int j = 0; j < NJ; j++) {
        cp_wait<1>();
        __syncthreads();
        if (j + 2 < NJ) fill((buf + 2 >= 3) ? buf - 1 : buf + 2, j + 2);
        cp_commit();

        const int jbase = j * 64;
        const __half* K = smh + buf * AT_BUF;
        const __half* V = K + KV_TILE;
        buf = (buf == 2) ? 0 : buf + 1;

        if (jbase > qrow0 + 31) continue;   // warp-uniform skip

        // ---- S = Q*K^T ----
        float sc[2][8][4];
        #pragma unroll
        for (int mt = 0; mt < 2; mt++)
            #pragma unroll
            for (int t = 0; t < 8; t++)
                #pragma unroll
                for (int e = 0; e < 4; e++) sc[mt][t][e] = 0.0f;

        #pragma unroll
        for (int kk = 0; kk < 4; kk++) {
            uint32_t kb[8][2];
            #pragma unroll
            for (int np = 0; np < 4; np++)
                ldm_x4(kb[2 * np][0], kb[2 * np][1], kb[2 * np + 1][0], kb[2 * np + 1][1],
                       K + (np * 16 + b_row) * AT_LD + kk * 16 + b_ko);
            #pragma unroll
            for (int mt = 0; mt < 2; mt++)
                #pragma unroll
                for (int nt = 0; nt < 8; nt++)
                    mma_f16(sc[mt][nt], aq[mt][kk], kb[nt][0], kb[nt][1]);
        }

        // ---- causal mask ----
        if (jbase + 63 > qrow0) {
            #pragma unroll
            for (int mt = 0; mt < 2; mt++) {
                const int qA = qrow0 + mt * 16 + g;
                #pragma unroll
                for (int t = 0; t < 8; t++) {
                    int cc0 = jbase + t * 8 + c2;
                    int cc1 = cc0 + 1;
                    if (cc0 > qA)     sc[mt][t][0] = -INFINITY;
                    if (cc1 > qA)     sc[mt][t][1] = -INFINITY;
                    if (cc0 > qA + 8) sc[mt][t][2] = -INFINITY;
                    if (cc1 > qA + 8) sc[mt][t][3] = -INFINITY;
                }
            }
        }

        // ---- softmax: running max + h2exp in log2 domain ----
        uint32_t sp[2][8][2];
        #pragma unroll
        for (int mt = 0; mt < 2; mt++) {
            float mxA = -INFINITY, mxB = -INFINITY;
            #pragma unroll
            for (int t = 0; t < 8; t++) {
                mxA = fmaxf(mxA, fmaxf(sc[mt][t][0], sc[mt][t][1]));
                mxB = fmaxf(mxB, fmaxf(sc[mt][t][2], sc[mt][t][3]));
            }
            #pragma unroll
            for (int o = 1; o <= 2; o <<= 1) {
                mxA = fmaxf(mxA, __shfl_xor_sync(0xffffffffu, mxA, o));
                mxB = fmaxf(mxB, __shfl_xor_sync(0xffffffffu, mxB, o));
            }
            const float mA2 = fmaxf(mA[mt], mxA);
            const float mB2 = fmaxf(mB[mt], mxB);

            // warp-vote rescale skip: if no row's max changed, alpha==1 everywhere
            const bool nochange = (mA2 == mA[mt]) && (mB2 == mB[mt]);
            if (!__all_sync(0xffffffffu, nochange)) {
                const float alA = ex2f_((mA[mt] - mA2) * L2E);
                const float alB = ex2f_((mB[mt] - mB2) * L2E);
                #pragma unroll
                for (int t = 0; t < 9; t++) {
                    oc[mt][t][0] *= alA; oc[mt][t][1] *= alA;
                    oc[mt][t][2] *= alB; oc[mt][t][3] *= alB;
                }
            }
            mA[mt] = mA2; mB[mt] = mB2;
            const float negA = -mA2 * L2E;
            const float negB = -mB2 * L2E;

            #pragma unroll
            for (int t = 0; t < 8; t++) {
                float d0 = fmaf(sc[mt][t][0], L2E, negA);
                float d1 = fmaf(sc[mt][t][1], L2E, negA);
                float d2 = fmaf(sc[mt][t][2], L2E, negB);
                float d3 = fmaf(sc[mt][t][3], L2E, negB);
                sp[mt][t][0] = h2exp2_u(pack_h2(d0, d1));
                sp[mt][t][1] = h2exp2_u(pack_h2(d2, d3));
            }
        }

        // ---- O (+l) += P * [V | 1] : 9 n-tiles, ldmatrix.trans ----
        #pragma unroll
        for (int kk = 0; kk < 4; kk++) {
            uint32_t vb[10][2];
            #pragma unroll
            for (int np = 0; np < 5; np++)
                ldm_x4_t(vb[2 * np][0], vb[2 * np][1], vb[2 * np + 1][0], vb[2 * np + 1][1],
                         V + (kk * 16 + vt_row) * AT_LD + np * 16 + vt_co);
            #pragma unroll
            for (int mt = 0; mt < 2; mt++) {
                uint32_t ap[4];
                ap[0] = sp[mt][2 * kk][0];
                ap[1] = sp[mt][2 * kk][1];
                ap[2] = sp[mt][2 * kk + 1][0];
                ap[3] = sp[mt][2 * kk + 1][1];
                #pragma unroll
                for (int nt = 0; nt < 9; nt++)
                    mma_f16(oc[mt][nt], ap, vb[nt][0], vb[nt][1]);
            }
        }
    }

    // ---- epilogue: l in oc[mt][8][0]/[2] at tig==0; broadcast within quad ----
    #pragma unroll
    for (int mt = 0; mt < 2; mt++) {
        const float lA = __shfl_sync(0xffffffffu, oc[mt][8][0], lane & ~3);
        const float lB = __shfl_sync(0xffffffffu, oc[mt][8][2], lane & ~3);
        const float iA = 1.0f / lA;
        const float iB = 1.0f / lB;
        __half* ob = out + (size_t)(b * SEQ + qt * BQ + w * 32 + mt * 16 + g) * CH + h * 64 + c2;
        #pragma unroll
        for (int t = 0; t < 8; t++) {
            *reinterpret_cast<__half2*>(ob + t * 8) =
                __floats2half2_rn(oc[mt][t][0] * iA, oc[mt][t][1] * iA);
            *reinterpret_cast<__half2*>(ob + 8 * CH + t * 8) =
                __floats2half2_rn(oc[mt][t][2] * iB, oc[mt][t][3] * iB);
        }
    }
}

// ---------------- launch ----------------
extern "C" void kernel_launch(void* const* d_in, const int* in_sizes, int n_in,
                              void* d_out, int out_size)
{
    const float* x     = (const float*)d_in[0];
    const float* w_qkv = (const float*)d_in[1];
    const float* w_out = (const float*)d_in[2];
    float* out = (float*)d_out;

    __half *qkvh, *attnh, *xh, *wqkvh, *wouth;
    cudaGetSymbolAddress((void**)&qkvh,  g_qkvh);
    cudaGetSymbolAddress((void**)&attnh, g_attnh);
    cudaGetSymbolAddress((void**)&xh,    g_xh);
    cudaGetSymbolAddress((void**)&wqkvh, g_wqkvh);
    cudaGetSymbolAddress((void**)&wouth, g_wouth);

    cudaFuncSetAttribute(gemm_f16_kernel<true, 128>,
                         cudaFuncAttributeMaxDynamicSharedMemorySize, GEMM_SMEM_128);
    cudaFuncSetAttribute(gemm_f16_kernel<false, 128>,
                         cudaFuncAttributeMaxDynamicSharedMemorySize, GEMM_SMEM_128);
    cudaFuncSetAttribute(attn_kernel, cudaFuncAttributeMaxDynamicSharedMemorySize, AT_SMEM_BYTES);

    // 0) single fused fp32->fp16 pre-pass
    f2h3_kernel<<<512, 256>>>(
        (const float4*)x,     (__half2*)xh,    (ROWS * CH) / 4,
        (const float4*)w_qkv, (__half2*)wqkvh, (CH * C3) / 4,
        (const float4*)w_out, (__half2*)wouth, (CH * CH) / 4);

    // 1) qkv = x @ w_qkv  -> fp16 [8192 x 3072]
    gemm_f16_kernel<true, 128><<<dim3(C3 / 128, ROWS / 128), 128, GEMM_SMEM_128>>>(
        xh, wqkvh, qkvh, C3, CH);

    // 2) flash attention -> fp16
    attn_kernel<<<dim3(SEQ / BQ, BATCH * NHEAD), 128, AT_SMEM_BYTES>>>(qkvh, attnh);

    // 3) out = attn @ w_out -> fp32 [8192 x 1024]
    gemm_f16_kernel<false, 128><<<dim3(CH / 128, ROWS / 128), 128, GEMM_SMEM_128>>>(
        attnh, wouth, out, CH, CH);
}

// round 13
// speedup vs baseline: 1.0175x; 1.0175x over previous
#include <cuda_runtime.h>
#include <cuda_fp16.h>
#include <math.h>
#include <stdint.h>

#define BATCH 4
#define SEQ   2048
#define CH    1024
#define NHEAD 16
#define DK    64
#define C3    3072
#define ROWS  (BATCH*SEQ)   // 8192

// ---------------- scratch ----------------
__device__ __align__(16) __half g_qkvh[(size_t)ROWS * C3];
__device__ __align__(16) __half g_attnh[(size_t)ROWS * CH];
__device__ __align__(16) __half g_xh[(size_t)ROWS * CH];
__device__ __align__(16) __half g_wqkvh[(size_t)CH * C3];
__device__ __align__(16) __half g_wouth[(size_t)CH * CH];

// ---------------- helpers ----------------
__device__ __forceinline__ void cp_async16(void* smem_dst, const void* gmem_src) {
    unsigned s = (unsigned)__cvta_generic_to_shared(smem_dst);
    asm volatile("cp.async.cg.shared.global [%0], [%1], 16;\n" :: "r"(s), "l"(gmem_src));
}
__device__ __forceinline__ void cp_commit() {
    asm volatile("cp.async.commit_group;\n" ::);
}
template<int N>
__device__ __forceinline__ void cp_wait() {
    asm volatile("cp.async.wait_group %0;\n" :: "n"(N));
}
__device__ __forceinline__ void mma_f16(float c[4], const uint32_t a[4], uint32_t b0, uint32_t b1) {
    asm volatile(
        "mma.sync.aligned.m16n8k16.row.col.f32.f16.f16.f32 "
        "{%0,%1,%2,%3}, {%4,%5,%6,%7}, {%8,%9}, {%0,%1,%2,%3};"
        : "+f"(c[0]), "+f"(c[1]), "+f"(c[2]), "+f"(c[3])
        : "r"(a[0]), "r"(a[1]), "r"(a[2]), "r"(a[3]), "r"(b0), "r"(b1));
}
// fp16-accumulator mma: c = {row g pair, row g+8 pair}, packed half2
__device__ __forceinline__ void mma_f16_h(uint32_t c[2], const uint32_t a[4], uint32_t b0, uint32_t b1) {
    asm volatile(
        "mma.sync.aligned.m16n8k16.row.col.f16.f16.f16.f16 "
        "{%0,%1}, {%2,%3,%4,%5}, {%6,%7}, {%0,%1};"
        : "+r"(c[0]), "+r"(c[1])
        : "r"(a[0]), "r"(a[1]), "r"(a[2]), "r"(a[3]), "r"(b0), "r"(b1));
}
__device__ __forceinline__ __half2 u2h(uint32_t u) { return *reinterpret_cast<__half2*>(&u); }
__device__ __forceinline__ uint32_t h2u(__half2 h) { return *reinterpret_cast<uint32_t*>(&h); }
__device__ __forceinline__ uint32_t h2exp2_u(uint32_t d2) {
    uint32_t r;
    asm("ex2.approx.f16x2 %0, %1;" : "=r"(r) : "r"(d2));
    return r;
}
__device__ __forceinline__ void ldm_x4(uint32_t& r0, uint32_t& r1, uint32_t& r2, uint32_t& r3,
                                       const __half* p) {
    uint32_t addr = (uint32_t)__cvta_generic_to_shared(p);
    asm volatile("ldmatrix.sync.aligned.m8n8.x4.shared.b16 {%0,%1,%2,%3}, [%4];"
        : "=r"(r0), "=r"(r1), "=r"(r2), "=r"(r3) : "r"(addr));
}
__device__ __forceinline__ void ldm_x4_t(uint32_t& r0, uint32_t& r1, uint32_t& r2, uint32_t& r3,
                                         const __half* p) {
    uint32_t addr = (uint32_t)__cvta_generic_to_shared(p);
    asm volatile("ldmatrix.sync.aligned.m8n8.x4.trans.shared.b16 {%0,%1,%2,%3}, [%4];"
        : "=r"(r0), "=r"(r1), "=r"(r2), "=r"(r3) : "r"(addr));
}

// ---------------- fused pre-pass: fp32 -> fp16 for x, w_qkv, w_out ----------------
__global__ void f2h3_kernel(const float4* __restrict__ a, __half2* __restrict__ ah, int na,
                            const float4* __restrict__ b, __half2* __restrict__ bh, int nb,
                            const float4* __restrict__ c, __half2* __restrict__ ch, int nc)
{
    int i = blockIdx.x * blockDim.x + threadIdx.x;
    const int stride = gridDim.x * blockDim.x;
    const int tot = na + nb + nc;
    for (; i < tot; i += stride) {
        const float4* src;
        __half2* dst;
        int k;
        if (i < na)            { src = a; dst = ah; k = i; }
        else if (i < na + nb)  { src = b; dst = bh; k = i - na; }
        else                   { src = c; dst = ch; k = i - na - nb; }
        float4 v = src[k];
        dst[2 * k]     = __floats2half2_rn(v.x, v.y);
        dst[2 * k + 1] = __floats2half2_rn(v.z, v.w);
    }
}

// ---------------- fp16 GEMM: C[M,N] = A[M,K] @ B[K,N] (R11 form) ----------------
#define GTK 32
#define GALD 40
#define G_ASTG (128 * GALD)           // 5120 halves

template<bool HALF_OUT, int TN>
__global__ void __launch_bounds__(128, 2) gemm_f16_kernel(
    const __half* __restrict__ A, const __half* __restrict__ B,
    void* __restrict__ Cout, int Ntot, int K)
{
    constexpr int WN   = TN / 2;
    constexpr int NT   = WN / 8;
    constexpr int NG   = WN / 16;
    constexpr int BLD  = TN + 8;
    constexpr int BSTG = GTK * BLD;
    constexpr int STG  = G_ASTG + BSTG;

    extern __shared__ __half sh[];
    const int tid = threadIdx.x;
    const int lane = tid & 31;
    const int wid = tid >> 5;
    const int wm = wid & 1;
    const int wn = wid >> 1;
    const int m0 = blockIdx.y * 128;
    const int n0 = blockIdx.x * TN;
    const int KT = K / GTK;
    const int g = lane >> 2;
    const int c2 = 2 * (lane & 3);

    const int a_row = lane & 15;
    const int a_ko  = (lane >> 4) * 8;
    const int vt_row = ((lane >> 3) & 1) * 8 + (lane & 7);
    const int vt_co  = (lane >> 4) * 8;

    auto fill = [&](int buf, int s) {
        __half* As = sh + buf * STG;
        __half* Bs = As + G_ASTG;
        const int k0 = s * GTK;
        #pragma unroll
        for (int j = 0; j < 4; j++) {
            int c = tid + j * 128;
            int row = c >> 2, chh = (c & 3) << 3;
            cp_async16(As + row * GALD + chh, A + (size_t)(m0 + row) * K + k0 + chh);
        }
        #pragma unroll
        for (int j = 0; j < TN / 32; j++) {
            int c = tid + j * 128;
            int row = c / (TN / 8);
            int chh = (c % (TN / 8)) * 8;
            cp_async16(Bs + row * BLD + chh, B + (size_t)(k0 + row) * Ntot + n0 + chh);
        }
    };

    float acc[4][NT][4];
    #pragma unroll
    for (int i = 0; i < 4; i++)
        #pragma unroll
        for (int j = 0; j < NT; j++)
            #pragma unroll
            for (int e = 0; e < 4; e++) acc[i][j][e] = 0.0f;

    fill(0, 0); cp_commit();
    fill(1, 1); cp_commit();
    fill(2, 2); cp_commit();

    for (int s = 0; s < KT; s++) {
        cp_wait<2>();
        __syncthreads();
        if (s + 3 < KT) fill((s + 3) & 3, s + 3);
        cp_commit();

        const __half* As = sh + (s & 3) * STG;
        const __half* Bs = As + G_ASTG;

        #pragma unroll
        for (int kk = 0; kk < 2; kk++) {
            uint32_t a[4][4];
            #pragma unroll
            for (int mt = 0; mt < 4; mt++)
                ldm_x4(a[mt][0], a[mt][1], a[mt][2], a[mt][3],
                       As + (wm * 64 + mt * 16 + a_row) * GALD + kk * 16 + a_ko);

            uint32_t bf[NT][2];
            #pragma unroll
            for (int ng = 0; ng < NG; ng++)
                ldm_x4_t(bf[2 * ng][0], bf[2 * ng][1], bf[2 * ng + 1][0], bf[2 * ng + 1][1],
                         Bs + (kk * 16 + vt_row) * BLD + wn * WN + ng * 16 + vt_co);

            #pragma unroll
            for (int mt = 0; mt < 4; mt++)
                #pragma unroll
                for (int nt = 0; nt < NT; nt++)
                    mma_f16(acc[mt][nt], a[mt], bf[nt][0], bf[nt][1]);
        }
    }

    #pragma unroll
    for (int mt = 0; mt < 4; mt++) {
        #pragma unroll
        for (int nt = 0; nt < NT; nt++) {
            const int row = m0 + wm * 64 + mt * 16 + g;
            const int col = n0 + wn * WN + nt * 8 + c2;
            if (HALF_OUT) {
                __half* Ch = (__half*)Cout;
                *reinterpret_cast<__half2*>(Ch + (size_t)row * Ntot + col) =
                    __floats2half2_rn(acc[mt][nt][0], acc[mt][nt][1]);
                *reinterpret_cast<__half2*>(Ch + (size_t)(row + 8) * Ntot + col) =
                    __floats2half2_rn(acc[mt][nt][2], acc[mt][nt][3]);
            } else {
                float* Cf = (float*)Cout;
                *reinterpret_cast<float2*>(Cf + (size_t)row * Ntot + col) =
                    make_float2(acc[mt][nt][0], acc[mt][nt][1]);
                *reinterpret_cast<float2*>(Cf + (size_t)(row + 8) * Ntot + col) =
                    make_float2(acc[mt][nt][2], acc[mt][nt][3]);
            }
        }
    }
}

#define GEMM_SMEM_128 ((G_ASTG + GTK * 136) * 2 * 4)   // 75776 bytes

// ---------------- Flash attention: fp16-accum QK + half2 softmax ----------------
#define BQ 128
#define AT_LD 88
#define KV_TILE (64 * AT_LD)
#define AT_BUF (2 * KV_TILE)
#define AT_SMEM_HALVES (3 * AT_BUF + BQ * AT_LD)
#define AT_SMEM_BYTES (AT_SMEM_HALVES * 2)          // 90112
#define L2E 1.4426950408889634f
#define NEGINF2 0xFC00FC00u

__global__ void __launch_bounds__(128, 2) attn_kernel(
    const __half* __restrict__ qkvh, __half* __restrict__ out)
{
    extern __shared__ __half smh[];
    const int tid = threadIdx.x;
    const int lane = tid & 31;
    const int w = tid >> 5;
    const int g = lane >> 2;
    const int c2 = 2 * (lane & 3);
    const int qt = gridDim.x - 1 - blockIdx.x;
    const int bh = blockIdx.y;
    const int b = bh >> 4;
    const int h = bh & 15;

    const int a_row = lane & 15;
    const int a_ko  = (lane >> 4) * 8;
    const int b_row = ((lane >> 4) * 8) + (lane & 7);
    const int b_ko  = ((lane >> 3) & 1) * 8;
    const int vt_row = ((lane >> 3) & 1) * 8 + (lane & 7);
    const int vt_co  = (lane >> 4) * 8;

    __half* Qs = smh + 3 * AT_BUF;
    const int NJ = 2 * qt + 2;

    const __half2 hl2e  = __float2half2_rn(L2E);
    const __half2 hnl2e = __float2half2_rn(-L2E);

    auto fill = [&](int buf, int j) {
        __half* K = smh + buf * AT_BUF;
        __half* V = K + KV_TILE;
        const __half* kg = qkvh + (size_t)(b * SEQ + j * 64) * C3 + CH + h * 64;
        #pragma unroll
        for (int i = 0; i < 4; i++) {
            int f = tid + i * 128;
            int r = f >> 3, ch = (f & 7) << 3;
            const __half* src = kg + (size_t)r * C3 + ch;
            cp_async16(K + r * AT_LD + ch, src);
            cp_async16(V + r * AT_LD + ch, src + CH);
        }
    };

    fill(0, 0); cp_commit();
    if (NJ > 1) fill(1, 1);
    cp_commit();

    // V pad columns (64..87), all 3 buffers: col 64 = 1 (l-column), rest 0
    for (int idx = tid; idx < 3 * 64 * 24; idx += 128) {
        int bufi = idx / (64 * 24);
        int rr = (idx % (64 * 24)) / 24;
        int cc = idx % 24;
        smh[bufi * AT_BUF + KV_TILE + rr * AT_LD + 64 + cc] =
            (cc == 0) ? __float2half(1.0f) : __float2half(0.0f);
    }

    // Q tile
    {
        const __half* gq = qkvh + (size_t)(b * SEQ + qt * BQ) * C3 + h * 64;
        #pragma unroll
        for (int f = tid; f < 1024; f += 128) {
            int r = f >> 3, ch = (f & 7) << 3;
            *reinterpret_cast<uint4*>(Qs + r * AT_LD + ch) =
                *reinterpret_cast<const uint4*>(gq + (size_t)r * C3 + ch);
        }
    }
    __syncthreads();

    // Q a-fragments, scaled by 1/8 (exact in fp16)
    uint32_t aq[2][4][4];
    {
        const __half2 sc8 = __float2half2_rn(0.125f);
        #pragma unroll
        for (int mt = 0; mt < 2; mt++)
            #pragma unroll
            for (int kk = 0; kk < 4; kk++) {
                ldm_x4(aq[mt][kk][0], aq[mt][kk][1], aq[mt][kk][2], aq[mt][kk][3],
                       Qs + (w * 32 + mt * 16 + a_row) * AT_LD + kk * 16 + a_ko);
                #pragma unroll
                for (int e = 0; e < 4; e++)
                    aq[mt][kk][e] = h2u(__hmul2(u2h(aq[mt][kk][e]), sc8));
            }
    }

    // oc[mt][0..7] = O accumulators; oc[mt][8] = l column (fp32, unchanged)
    float oc[2][9][4];
    #pragma unroll
    for (int mt = 0; mt < 2; mt++)
        #pragma unroll
        for (int t = 0; t < 9; t++)
            #pragma unroll
            for (int e = 0; e < 4; e++) oc[mt][t][e] = 0.0f;
    __half2 mold2[2];
    mold2[0] = u2h(NEGINF2);
    mold2[1] = u2h(NEGINF2);

    const int qrow0 = qt * BQ + w * 32;

    int buf = 0;
    for (int j = 0; j < NJ; j++) {
        cp_wait<1>();
        __syncthreads();
        if (j + 2 < NJ) fill((buf + 2 >= 3) ? buf - 1 : buf + 2, j + 2);
        cp_commit();

        const int jbase = j * 64;
        const __half* K = smh + buf * AT_BUF;
        const __half* V = K + KV_TILE;
        buf = (buf == 2) ? 0 : buf + 1;

        if (jbase > qrow0 + 31) continue;   // warp-uniform skip

        // ---- S = Q*K^T : fp16 accumulators (2x tensor rate) ----
        uint32_t sc2[2][8][2];
        #pragma unroll
        for (int mt = 0; mt < 2; mt++)
            #pragma unroll
            for (int t = 0; t < 8; t++) {
                sc2[mt][t][0] = 0u;
                sc2[mt][t][1] = 0u;
            }

        #pragma unroll
        for (int kk = 0; kk < 4; kk++) {
            uint32_t kb[8][2];
            #pragma unroll
            for (int np = 0; np < 4; np++)
                ldm_x4(kb[2 * np][0], kb[2 * np][1], kb[2 * np + 1][0], kb[2 * np + 1][1],
                       K + (np * 16 + b_row) * AT_LD + kk * 16 + b_ko);
            #pragma unroll
            for (int mt = 0; mt < 2; mt++)
                #pragma unroll
                for (int nt = 0; nt < 8; nt++)
                    mma_f16_h(sc2[mt][nt], aq[mt][kk], kb[nt][0], kb[nt][1]);
        }

        // ---- causal mask: additive -inf in half2 ----
        if (jbase + 63 > qrow0) {
            #pragma unroll
            for (int mt = 0; mt < 2; mt++) {
                const int qA = qrow0 + mt * 16 + g;
                #pragma unroll
                for (int t = 0; t < 8; t++) {
                    const int cc0 = jbase + t * 8 + c2;
                    const int cc1 = cc0 + 1;
                    uint32_t m0 = (cc0 > qA ? 0xFC00u : 0u) | (cc1 > qA ? 0xFC000000u : 0u);
                    uint32_t m1 = (cc0 > qA + 8 ? 0xFC00u : 0u) | (cc1 > qA + 8 ? 0xFC000000u : 0u);
                    sc2[mt][t][0] = h2u(__hadd2(u2h(sc2[mt][t][0]), u2h(m0)));
                    sc2[mt][t][1] = h2u(__hadd2(u2h(sc2[mt][t][1]), u2h(m1)));
                }
            }
        }

        // ---- softmax entirely in half2 (log2 domain); P written in place ----
        #pragma unroll
        for (int mt = 0; mt < 2; mt++) {
            __half2 mxA = u2h(NEGINF2), mxB = u2h(NEGINF2);
            #pragma unroll
            for (int t = 0; t < 8; t++) {
                mxA = __hmax2(mxA, u2h(sc2[mt][t][0]));
                mxB = __hmax2(mxB, u2h(sc2[mt][t][1]));
            }
            __half2 m2 = __halves2half2(__hmax(__low2half(mxA), __high2half(mxA)),
                                        __hmax(__low2half(mxB), __high2half(mxB)));
            #pragma unroll
            for (int o = 1; o <= 2; o <<= 1)
                m2 = __hmax2(m2, u2h(__shfl_xor_sync(0xffffffffu, h2u(m2), o)));
            const __half2 mold = mold2[mt];
            const __half2 mnew = __hmax2(m2, mold);

            const bool noch = (h2u(mnew) == h2u(mold));
            if (!__all_sync(0xffffffffu, noch)) {
                // alpha = exp2((mold - mnew)*L2E); mold=-inf -> alpha=0 (oc is 0 then)
                __half2 al = u2h(h2exp2_u(h2u(__hmul2(__hsub2(mold, mnew), hl2e))));
                const float alA = __half2float(__low2half(al));
                const float alB = __half2float(__high2half(al));
                #pragma unroll
                for (int t = 0; t < 9; t++) {
                    oc[mt][t][0] *= alA; oc[mt][t][1] *= alA;
                    oc[mt][t][2] *= alB; oc[mt][t][3] *= alB;
                }
            }
            mold2[mt] = mnew;

            const __half2 nm = __hmul2(mnew, hnl2e);   // {-mA*L2E, -mB*L2E}
            const __half2 nmA = __half2half2(__low2half(nm));
            const __half2 nmB = __half2half2(__high2half(nm));
            #pragma unroll
            for (int t = 0; t < 8; t++) {
                sc2[mt][t][0] = h2exp2_u(h2u(__hfma2(u2h(sc2[mt][t][0]), hl2e, nmA)));
                sc2[mt][t][1] = h2exp2_u(h2u(__hfma2(u2h(sc2[mt][t][1]), hl2e, nmB)));
            }
        }

        // ---- O (+l) += P * [V | 1] : P fragments are sc2 directly ----
        #pragma unroll
        for (int kk = 0; kk < 4; kk++) {
            uint32_t vb[10][2];
            #pragma unroll
            for (int np = 0; np < 5; np++)
                ldm_x4_t(vb[2 * np][0], vb[2 * np][1], vb[2 * np + 1][0], vb[2 * np + 1][1],
                         V + (kk * 16 + vt_row) * AT_LD + np * 16 + vt_co);
            #pragma unroll
            for (int mt = 0; mt < 2; mt++) {
                uint32_t ap[4];
                ap[0] = sc2[mt][2 * kk][0];
                ap[1] = sc2[mt][2 * kk][1];
                ap[2] = sc2[mt][2 * kk + 1][0];
                ap[3] = sc2[mt][2 * kk + 1][1];
                #pragma unroll
                for (int nt = 0; nt < 9; nt++)
                    mma_f16(oc[mt][nt], ap, vb[nt][0], vb[nt][1]);
            }
        }
    }

    // ---- epilogue: l in oc[mt][8][0]/[2] at tig==0; broadcast within quad ----
    #pragma unroll
    for (int mt = 0; mt < 2; mt++) {
        const float lA = __shfl_sync(0xffffffffu, oc[mt][8][0], lane & ~3);
        const float lB = __shfl_sync(0xffffffffu, oc[mt][8][2], lane & ~3);
        const float iA = 1.0f / lA;
        const float iB = 1.0f / lB;
        __half* ob = out + (size_t)(b * SEQ + qt * BQ + w * 32 + mt * 16 + g) * CH + h * 64 + c2;
        #pragma unroll
        for (int t = 0; t < 8; t++) {
            *reinterpret_cast<__half2*>(ob + t * 8) =
                __floats2half2_rn(oc[mt][t][0] * iA, oc[mt][t][1] * iA);
            *reinterpret_cast<__half2*>(ob + 8 * CH + t * 8) =
                __floats2half2_rn(oc[mt][t][2] * iB, oc[mt][t][3] * iB);
        }
    }
}

// ---------------- launch ----------------
extern "C" void kernel_launch(void* const* d_in, const int* in_sizes, int n_in,
                              void* d_out, int out_size)
{
    const float* x     = (const float*)d_in[0];
    const float* w_qkv = (const float*)d_in[1];
    const float* w_out = (const float*)d_in[2];
    float* out = (float*)d_out;

    __half *qkvh, *attnh, *xh, *wqkvh, *wouth;
    cudaGetSymbolAddress((void**)&qkvh,  g_qkvh);
    cudaGetSymbolAddress((void**)&attnh, g_attnh);
    cudaGetSymbolAddress((void**)&xh,    g_xh);
    cudaGetSymbolAddress((void**)&wqkvh, g_wqkvh);
    cudaGetSymbolAddress((void**)&wouth, g_wouth);

    cudaFuncSetAttribute(gemm_f16_kernel<true, 128>,
                         cudaFuncAttributeMaxDynamicSharedMemorySize, GEMM_SMEM_128);
    cudaFuncSetAttribute(gemm_f16_kernel<false, 128>,
                         cudaFuncAttributeMaxDynamicSharedMemorySize, GEMM_SMEM_128);
    cudaFuncSetAttribute(attn_kernel, cudaFuncAttributeMaxDynamicSharedMemorySize, AT_SMEM_BYTES);

    // 0) single fused fp32->fp16 pre-pass
    f2h3_kernel<<<512, 256>>>(
        (const float4*)x,     (__half2*)xh,    (ROWS * CH) / 4,
        (const float4*)w_qkv, (__half2*)wqkvh, (CH * C3) / 4,
        (const float4*)w_out, (__half2*)wouth, (CH * CH) / 4);

    // 1) qkv = x @ w_qkv  -> fp16 [8192 x 3072]
    gemm_f16_kernel<true, 128><<<dim3(C3 / 128, ROWS / 128), 128, GEMM_SMEM_128>>>(
        xh, wqkvh, qkvh, C3, CH);

    // 2) flash attention -> fp16
    attn_kernel<<<dim3(SEQ / BQ, BATCH * NHEAD), 128, AT_SMEM_BYTES>>>(qkvh, attnh);

    // 3) out = attn @ w_out -> fp32 [8192 x 1024]
    gemm_f16_kernel<false, 128><<<dim3(CH / 128, ROWS / 128), 128, GEMM_SMEM_128>>>(
        attnh, wouth, out, CH, CH);
}